// round 1
// baseline (speedup 1.0000x reference)
#include <cuda_runtime.h>

// Problem constants
#define Nn     50000
#define Dd     64
#define Ee     800000
#define Bb     50
#define NMAXx  1000
#define Cc     100

// Scratch (device globals; no allocation allowed)
__device__ float g_xa[Nn * Dd];          // x @ W_ma[:64] + b_ma
__device__ float g_acc[Nn * Dd];         // (1+eps1)*x + segment_sum(msg)
__device__ float g_up[Nn * Dd];          // einsum result (flat [B*NMAX, D])
__device__ float g_msgup[Bb * Cc * Dd];  // relu(attr1 @ W_mu + b_mu)

// ---------------------------------------------------------------------------
// Kernel 1: g_xa = x @ W_ma[0:64] + b_ma ;  g_acc = (1+eps1)*x
// Tile: 64 rows x 64 cols, 256 threads, 4x4 microtile.
// ---------------------------------------------------------------------------
__global__ __launch_bounds__(256) void k_node_pre(
    const float* __restrict__ x, const float* __restrict__ W_ma,
    const float* __restrict__ b_ma, const float* __restrict__ eps1)
{
    __shared__ float Xs[64 * 68];
    __shared__ float Ws[64 * 68];
    __shared__ float bs[64];
    const int t = threadIdx.x;
    const int row0 = blockIdx.x * 64;

    for (int i = t; i < 64 * 16; i += 256) {
        int k = i / 16, c = (i % 16) * 4;
        *(float4*)(Ws + k * 68 + c) = *(const float4*)(W_ma + k * 64 + c);
    }
    if (t < 64) bs[t] = b_ma[t];
    for (int i = t; i < 64 * 16; i += 256) {
        int r = i / 16, c = (i % 16) * 4;
        int gr = row0 + r;
        float4 v = make_float4(0.f, 0.f, 0.f, 0.f);
        if (gr < Nn) v = *(const float4*)(x + gr * 64 + c);
        *(float4*)(Xs + r * 68 + c) = v;
    }
    __syncthreads();

    const int r0 = (t / 16) * 4, c0 = (t % 16) * 4;
    float acc[4][4];
#pragma unroll
    for (int i = 0; i < 4; i++)
#pragma unroll
        for (int j = 0; j < 4; j++) acc[i][j] = 0.f;

#pragma unroll
    for (int k = 0; k < 64; k += 4) {
        float4 a4[4];
#pragma unroll
        for (int i = 0; i < 4; i++) a4[i] = *(float4*)(Xs + (r0 + i) * 68 + k);
#pragma unroll
        for (int kk = 0; kk < 4; kk++) {
            float4 b4 = *(float4*)(Ws + (k + kk) * 68 + c0);
#pragma unroll
            for (int i = 0; i < 4; i++) {
                float a = ((const float*)&a4[i])[kk];
                acc[i][0] += a * b4.x; acc[i][1] += a * b4.y;
                acc[i][2] += a * b4.z; acc[i][3] += a * b4.w;
            }
        }
    }

    const float e1 = 1.0f + eps1[0];
#pragma unroll
    for (int i = 0; i < 4; i++) {
        int gr = row0 + r0 + i;
        if (gr < Nn) {
            float4 o;
            o.x = acc[i][0] + bs[c0 + 0];
            o.y = acc[i][1] + bs[c0 + 1];
            o.z = acc[i][2] + bs[c0 + 2];
            o.w = acc[i][3] + bs[c0 + 3];
            *(float4*)(g_xa + gr * 64 + c0) = o;
            float4 xv = *(float4*)(Xs + (r0 + i) * 68 + c0);
            float4 av = make_float4(e1 * xv.x, e1 * xv.y, e1 * xv.z, e1 * xv.w);
            *(float4*)(g_acc + gr * 64 + c0) = av;
        }
    }
}

// ---------------------------------------------------------------------------
// Kernel 2: g_msgup = relu(attr1 @ W_mu + b_mu)   rows M = B*C = 5000
// ---------------------------------------------------------------------------
__global__ __launch_bounds__(256) void k_mlp_up(
    const float* __restrict__ attr1, const float* __restrict__ W_mu,
    const float* __restrict__ b_mu)
{
    __shared__ float As[64 * 68];
    __shared__ float Ws[64 * 68];
    __shared__ float bs[64];
    const int t = threadIdx.x;
    const int row0 = blockIdx.x * 64;
    const int M = Bb * Cc;

    for (int i = t; i < 64 * 16; i += 256) {
        int k = i / 16, c = (i % 16) * 4;
        *(float4*)(Ws + k * 68 + c) = *(const float4*)(W_mu + k * 64 + c);
    }
    if (t < 64) bs[t] = b_mu[t];
    for (int i = t; i < 64 * 16; i += 256) {
        int r = i / 16, c = (i % 16) * 4;
        int gr = row0 + r;
        float4 v = make_float4(0.f, 0.f, 0.f, 0.f);
        if (gr < M) v = *(const float4*)(attr1 + gr * 64 + c);
        *(float4*)(As + r * 68 + c) = v;
    }
    __syncthreads();

    const int r0 = (t / 16) * 4, c0 = (t % 16) * 4;
    float acc[4][4];
#pragma unroll
    for (int i = 0; i < 4; i++)
#pragma unroll
        for (int j = 0; j < 4; j++) acc[i][j] = 0.f;

#pragma unroll
    for (int k = 0; k < 64; k += 4) {
        float4 a4[4];
#pragma unroll
        for (int i = 0; i < 4; i++) a4[i] = *(float4*)(As + (r0 + i) * 68 + k);
#pragma unroll
        for (int kk = 0; kk < 4; kk++) {
            float4 b4 = *(float4*)(Ws + (k + kk) * 68 + c0);
#pragma unroll
            for (int i = 0; i < 4; i++) {
                float a = ((const float*)&a4[i])[kk];
                acc[i][0] += a * b4.x; acc[i][1] += a * b4.y;
                acc[i][2] += a * b4.z; acc[i][3] += a * b4.w;
            }
        }
    }

#pragma unroll
    for (int i = 0; i < 4; i++) {
        int gr = row0 + r0 + i;
        if (gr < M) {
            float4 o;
            o.x = fmaxf(acc[i][0] + bs[c0 + 0], 0.f);
            o.y = fmaxf(acc[i][1] + bs[c0 + 1], 0.f);
            o.z = fmaxf(acc[i][2] + bs[c0 + 2], 0.f);
            o.w = fmaxf(acc[i][3] + bs[c0 + 3], 0.f);
            *(float4*)(g_msgup + gr * 64 + c0) = o;
        }
    }
}

// ---------------------------------------------------------------------------
// Kernel 3: g_up[b,n,:] = sum_c nc1[b,n,c] * g_msgup[b,c,:]
// grid (16, 50), 64-row tiles, K=100.
// ---------------------------------------------------------------------------
__global__ __launch_bounds__(256) void k_upagg(const float* __restrict__ nc1)
{
    extern __shared__ float sm[];
    float* Ns = sm;              // 64 x 104
    float* Ms = sm + 64 * 104;   // 100 x 68
    const int t = threadIdx.x;
    const int b = blockIdx.y;
    const int row0 = blockIdx.x * 64;

    for (int i = t; i < 64 * 25; i += 256) {
        int r = i / 25, c = (i % 25) * 4;
        int gr = row0 + r;
        float4 v = make_float4(0.f, 0.f, 0.f, 0.f);
        if (gr < NMAXx)
            v = *(const float4*)(nc1 + ((size_t)b * NMAXx + gr) * Cc + c);
        *(float4*)(Ns + r * 104 + c) = v;
    }
    for (int i = t; i < 100 * 16; i += 256) {
        int r = i / 16, c = (i % 16) * 4;
        *(float4*)(Ms + r * 68 + c) =
            *(const float4*)(g_msgup + ((size_t)b * Cc + r) * 64 + c);
    }
    __syncthreads();

    const int r0 = (t / 16) * 4, c0 = (t % 16) * 4;
    float acc[4][4];
#pragma unroll
    for (int i = 0; i < 4; i++)
#pragma unroll
        for (int j = 0; j < 4; j++) acc[i][j] = 0.f;

#pragma unroll
    for (int k = 0; k < 100; k += 4) {
        float4 a4[4];
#pragma unroll
        for (int i = 0; i < 4; i++) a4[i] = *(float4*)(Ns + (r0 + i) * 104 + k);
#pragma unroll
        for (int kk = 0; kk < 4; kk++) {
            float4 b4 = *(float4*)(Ms + (k + kk) * 68 + c0);
#pragma unroll
            for (int i = 0; i < 4; i++) {
                float a = ((const float*)&a4[i])[kk];
                acc[i][0] += a * b4.x; acc[i][1] += a * b4.y;
                acc[i][2] += a * b4.z; acc[i][3] += a * b4.w;
            }
        }
    }

#pragma unroll
    for (int i = 0; i < 4; i++) {
        int gr = row0 + r0 + i;
        if (gr < NMAXx) {
            float4 o = make_float4(acc[i][0], acc[i][1], acc[i][2], acc[i][3]);
            *(float4*)(g_up + ((size_t)b * NMAXx + gr) * 64 + c0) = o;
        }
    }
}

// ---------------------------------------------------------------------------
// Kernel 4 (dominant): per 128-edge tile: EW = e_tile @ W_ma[64:128];
// msg = relu(g_xa[src] + EW); atomicAdd into g_acc[dst].
// 8x4 microtile per thread. E = 6250 * 128 exactly.
// ---------------------------------------------------------------------------
__global__ __launch_bounds__(256) void k_edge(
    const float* __restrict__ e, const int* __restrict__ ei,
    const float* __restrict__ W_ma)
{
    extern __shared__ float sm[];
    float* Es = sm;             // 128 x 68
    float* Ws = sm + 128 * 68;  // 64 x 68
    const int t = threadIdx.x;
    const int e0 = blockIdx.x * 128;

    for (int i = t; i < 64 * 16; i += 256) {
        int k = i / 16, c = (i % 16) * 4;
        *(float4*)(Ws + k * 68 + c) = *(const float4*)(W_ma + (64 + k) * 64 + c);
    }
    for (int i = t; i < 128 * 16; i += 256) {
        int r = i / 16, c = (i % 16) * 4;
        *(float4*)(Es + r * 68 + c) = *(const float4*)(e + (size_t)(e0 + r) * 64 + c);
    }
    __syncthreads();

    const int r0 = (t / 16) * 8, c0 = (t % 16) * 4;
    float acc[8][4];
#pragma unroll
    for (int i = 0; i < 8; i++)
#pragma unroll
        for (int j = 0; j < 4; j++) acc[i][j] = 0.f;

#pragma unroll
    for (int k = 0; k < 64; k += 4) {
        float4 a4[8];
#pragma unroll
        for (int i = 0; i < 8; i++) a4[i] = *(float4*)(Es + (r0 + i) * 68 + k);
#pragma unroll
        for (int kk = 0; kk < 4; kk++) {
            float4 b4 = *(float4*)(Ws + (k + kk) * 68 + c0);
#pragma unroll
            for (int i = 0; i < 8; i++) {
                float a = ((const float*)&a4[i])[kk];
                acc[i][0] += a * b4.x; acc[i][1] += a * b4.y;
                acc[i][2] += a * b4.z; acc[i][3] += a * b4.w;
            }
        }
    }

    const int* __restrict__ srcp = ei;
    const int* __restrict__ dstp = ei + Ee;
#pragma unroll
    for (int i = 0; i < 8; i++) {
        int er = e0 + r0 + i;
        int s = srcp[er];
        int d = dstp[er];
        float4 xa4 = *(const float4*)(g_xa + (size_t)s * 64 + c0);
        float v0 = fmaxf(acc[i][0] + xa4.x, 0.f);
        float v1 = fmaxf(acc[i][1] + xa4.y, 0.f);
        float v2 = fmaxf(acc[i][2] + xa4.z, 0.f);
        float v3 = fmaxf(acc[i][3] + xa4.w, 0.f);
        float* dp = g_acc + (size_t)d * 64 + c0;
        atomicAdd(dp + 0, v0);
        atomicAdd(dp + 1, v1);
        atomicAdd(dp + 2, v2);
        atomicAdd(dp + 3, v3);
    }
}

// ---------------------------------------------------------------------------
// Kernel 5 (fused tail): h1 = relu(g_acc @ W_ua + b_ua);
// h2 = relu((g_up[x_idx] + (1+eps2)*x) @ W_uu + b_uu);
// out = h1 @ W_c[0:64] + h2 @ W_c[64:128] + b_c
// ---------------------------------------------------------------------------
__global__ __launch_bounds__(256) void k_final(
    const float* __restrict__ x, const int* __restrict__ x_idx,
    const float* __restrict__ eps2,
    const float* __restrict__ W_ua, const float* __restrict__ b_ua,
    const float* __restrict__ W_uu, const float* __restrict__ b_uu,
    const float* __restrict__ W_c, const float* __restrict__ b_c,
    float* __restrict__ out)
{
    extern __shared__ float sm[];
    float* A1  = sm;
    float* A2  = A1 + 64 * 68;
    float* Wua = A2 + 64 * 68;
    float* Wuu = Wua + 64 * 68;
    float* Wc1 = Wuu + 64 * 68;
    float* Wc2 = Wc1 + 64 * 68;
    __shared__ float bua[64], buu[64], bcs[64];

    const int t = threadIdx.x;
    const int row0 = blockIdx.x * 64;
    const float e2 = 1.0f + eps2[0];

    for (int i = t; i < 64 * 16; i += 256) {
        int k = i / 16, c = (i % 16) * 4;
        *(float4*)(Wua + k * 68 + c) = *(const float4*)(W_ua + k * 64 + c);
        *(float4*)(Wuu + k * 68 + c) = *(const float4*)(W_uu + k * 64 + c);
        *(float4*)(Wc1 + k * 68 + c) = *(const float4*)(W_c + k * 64 + c);
        *(float4*)(Wc2 + k * 68 + c) = *(const float4*)(W_c + (64 + k) * 64 + c);
    }
    if (t < 64) { bua[t] = b_ua[t]; buu[t] = b_uu[t]; bcs[t] = b_c[t]; }

    for (int i = t; i < 64 * 16; i += 256) {
        int r = i / 16, c = (i % 16) * 4;
        int gr = row0 + r;
        float4 a1 = make_float4(0.f, 0.f, 0.f, 0.f);
        float4 a2 = make_float4(0.f, 0.f, 0.f, 0.f);
        if (gr < Nn) {
            a1 = *(const float4*)(g_acc + (size_t)gr * 64 + c);
            int xi = x_idx[gr];
            float4 u  = *(const float4*)(g_up + (size_t)xi * 64 + c);
            float4 xv = *(const float4*)(x + (size_t)gr * 64 + c);
            a2 = make_float4(u.x + e2 * xv.x, u.y + e2 * xv.y,
                             u.z + e2 * xv.z, u.w + e2 * xv.w);
        }
        *(float4*)(A1 + r * 68 + c) = a1;
        *(float4*)(A2 + r * 68 + c) = a2;
    }
    __syncthreads();

    const int r0 = (t / 16) * 4, c0 = (t % 16) * 4;
    float h1[4][4], h2[4][4];
#pragma unroll
    for (int i = 0; i < 4; i++)
#pragma unroll
        for (int j = 0; j < 4; j++) { h1[i][j] = 0.f; h2[i][j] = 0.f; }

#pragma unroll
    for (int k = 0; k < 64; k += 4) {
        float4 a14[4], a24[4];
#pragma unroll
        for (int i = 0; i < 4; i++) {
            a14[i] = *(float4*)(A1 + (r0 + i) * 68 + k);
            a24[i] = *(float4*)(A2 + (r0 + i) * 68 + k);
        }
#pragma unroll
        for (int kk = 0; kk < 4; kk++) {
            float4 b1 = *(float4*)(Wua + (k + kk) * 68 + c0);
            float4 b2 = *(float4*)(Wuu + (k + kk) * 68 + c0);
#pragma unroll
            for (int i = 0; i < 4; i++) {
                float a = ((const float*)&a14[i])[kk];
                float b = ((const float*)&a24[i])[kk];
                h1[i][0] += a * b1.x; h1[i][1] += a * b1.y;
                h1[i][2] += a * b1.z; h1[i][3] += a * b1.w;
                h2[i][0] += b * b2.x; h2[i][1] += b * b2.y;
                h2[i][2] += b * b2.z; h2[i][3] += b * b2.w;
            }
        }
    }
#pragma unroll
    for (int i = 0; i < 4; i++)
#pragma unroll
        for (int j = 0; j < 4; j++) {
            h1[i][j] = fmaxf(h1[i][j] + bua[c0 + j], 0.f);
            h2[i][j] = fmaxf(h2[i][j] + buu[c0 + j], 0.f);
        }
    __syncthreads();  // all reads of A1/A2 done
#pragma unroll
    for (int i = 0; i < 4; i++)
#pragma unroll
        for (int j = 0; j < 4; j++) {
            A1[(r0 + i) * 68 + c0 + j] = h1[i][j];
            A2[(r0 + i) * 68 + c0 + j] = h2[i][j];
        }
    __syncthreads();

    float o[4][4];
#pragma unroll
    for (int i = 0; i < 4; i++)
#pragma unroll
        for (int j = 0; j < 4; j++) o[i][j] = 0.f;

#pragma unroll
    for (int k = 0; k < 64; k += 4) {
        float4 a14[4], a24[4];
#pragma unroll
        for (int i = 0; i < 4; i++) {
            a14[i] = *(float4*)(A1 + (r0 + i) * 68 + k);
            a24[i] = *(float4*)(A2 + (r0 + i) * 68 + k);
        }
#pragma unroll
        for (int kk = 0; kk < 4; kk++) {
            float4 b1 = *(float4*)(Wc1 + (k + kk) * 68 + c0);
            float4 b2 = *(float4*)(Wc2 + (k + kk) * 68 + c0);
#pragma unroll
            for (int i = 0; i < 4; i++) {
                float a = ((const float*)&a14[i])[kk];
                float b = ((const float*)&a24[i])[kk];
                o[i][0] += a * b1.x + b * b2.x;
                o[i][1] += a * b1.y + b * b2.y;
                o[i][2] += a * b1.z + b * b2.z;
                o[i][3] += a * b1.w + b * b2.w;
            }
        }
    }

#pragma unroll
    for (int i = 0; i < 4; i++) {
        int gr = row0 + r0 + i;
        if (gr < Nn) {
            float4 ov;
            ov.x = o[i][0] + bcs[c0 + 0];
            ov.y = o[i][1] + bcs[c0 + 1];
            ov.z = o[i][2] + bcs[c0 + 2];
            ov.w = o[i][3] + bcs[c0 + 3];
            *(float4*)(out + (size_t)gr * 64 + c0) = ov;
        }
    }
}

// ---------------------------------------------------------------------------
extern "C" void kernel_launch(void* const* d_in, const int* in_sizes, int n_in,
                              void* d_out, int out_size)
{
    const float* x     = (const float*)d_in[0];
    const float* e     = (const float*)d_in[1];
    const int*   ei    = (const int*)d_in[2];
    const float* attr1 = (const float*)d_in[3];
    const float* nc1   = (const float*)d_in[4];
    const int*   x_idx = (const int*)d_in[5];
    const float* eps1  = (const float*)d_in[6];
    const float* eps2  = (const float*)d_in[7];
    const float* W_ma  = (const float*)d_in[8];
    const float* b_ma  = (const float*)d_in[9];
    const float* W_mu  = (const float*)d_in[10];
    const float* b_mu  = (const float*)d_in[11];
    const float* W_ua  = (const float*)d_in[12];
    const float* b_ua  = (const float*)d_in[13];
    const float* W_uu  = (const float*)d_in[14];
    const float* b_uu  = (const float*)d_in[15];
    const float* W_c   = (const float*)d_in[16];
    const float* b_c   = (const float*)d_in[17];
    float* out = (float*)d_out;

    const int SMEM_UP   = (64 * 104 + 100 * 68) * 4;   // 53824
    const int SMEM_EDGE = (128 * 68 + 64 * 68) * 4;    // 52224
    const int SMEM_FIN  = (6 * 64 * 68) * 4;           // 104448

    cudaFuncSetAttribute(k_upagg, cudaFuncAttributeMaxDynamicSharedMemorySize, SMEM_UP);
    cudaFuncSetAttribute(k_edge,  cudaFuncAttributeMaxDynamicSharedMemorySize, SMEM_EDGE);
    cudaFuncSetAttribute(k_final, cudaFuncAttributeMaxDynamicSharedMemorySize, SMEM_FIN);

    k_node_pre<<<(Nn + 63) / 64, 256>>>(x, W_ma, b_ma, eps1);
    k_mlp_up<<<(Bb * Cc + 63) / 64, 256>>>(attr1, W_mu, b_mu);
    k_upagg<<<dim3((NMAXx + 63) / 64, Bb), 256, SMEM_UP>>>(nc1);
    k_edge<<<Ee / 128, 256, SMEM_EDGE>>>(e, ei, W_ma);
    k_final<<<(Nn + 63) / 64, 256, SMEM_FIN>>>(x, x_idx, eps2, W_ua, b_ua,
                                               W_uu, b_uu, W_c, b_c, out);
}